// round 11
// baseline (speedup 1.0000x reference)
#include <cuda_runtime.h>
#include <cuda_bf16.h>
#include <cstddef>

#define Bn 2
#define Cc 64
#define Hh 256
#define Ww 256
#define HW (Hh*Ww)

typedef unsigned long long ull;

__device__ float g_A[(size_t)Bn*Cc*HW];
__device__ float g_B[(size_t)Bn*Cc*HW];
__device__ float g_WU[6*64*16*64];     // Winograd U: [layer][ci][u16][co64]

__device__ __forceinline__ ull pack2(float lo, float hi) {
    ull r; asm("mov.b64 %0, {%1, %2};" : "=l"(r) : "f"(lo), "f"(hi)); return r;
}
__device__ __forceinline__ ull dup2(float v) {
    ull r; asm("mov.b64 %0, {%1, %1};" : "=l"(r) : "f"(v)); return r;
}
__device__ __forceinline__ void unpack2(ull v, float& lo, float& hi) {
    asm("mov.b64 {%0, %1}, %2;" : "=f"(lo), "=f"(hi) : "l"(v));
}
__device__ __forceinline__ ull ffma2(ull a, ull b, ull c) {
    ull d; asm("fma.rn.f32x2 %0, %1, %2, %3;" : "=l"(d) : "l"(a), "l"(b), "l"(c)); return d;
}
__device__ __forceinline__ ull add2(ull a, ull b) {
    ull d; asm("add.rn.f32x2 %0, %1, %2;" : "=l"(d) : "l"(a), "l"(b)); return d;
}
__device__ __forceinline__ ull sub2(ull a, ull b) {
    ull d; asm("sub.rn.f32x2 %0, %1, %2;" : "=l"(d) : "l"(a), "l"(b)); return d;
}
__device__ __forceinline__ unsigned smem_u32(const void* p) {
    unsigned a;
    asm("{ .reg .u64 t; cvta.to.shared.u64 t, %1; cvt.u32.u64 %0, t; }" : "=r"(a) : "l"(p));
    return a;
}
__device__ __forceinline__ void cp_async4(unsigned dst, const void* src, int sz) {
    asm volatile("cp.async.ca.shared.global [%0], [%1], 4, %2;" :: "r"(dst), "l"(src), "r"(sz) : "memory");
}
__device__ __forceinline__ void cp_async16(unsigned dst, const void* src) {
    asm volatile("cp.async.cg.shared.global [%0], [%1], 16;" :: "r"(dst), "l"(src) : "memory");
}
__device__ __forceinline__ void cp_commit() { asm volatile("cp.async.commit_group;" ::: "memory"); }
template<int N> __device__ __forceinline__ void cp_wait() {
    asm volatile("cp.async.wait_group %0;" :: "n"(N) : "memory");
}

// ---- one-shot Winograd weight transform U = G g G^T ----
__global__ void pack_wu_k(const float* __restrict__ w0, const float* __restrict__ w1,
                          const float* __restrict__ w2, const float* __restrict__ w3,
                          const float* __restrict__ w4, const float* __restrict__ w5,
                          float* __restrict__ wu)
{
    int idx = blockIdx.x*256 + threadIdx.x;
    if (idx >= 6*64*64) return;
    int layer = idx / 4096; int r = idx - layer*4096;
    int ci = r >> 6, co = r & 63;
    const float* w = (layer==0)?w0:(layer==1)?w1:(layer==2)?w2:
                     (layer==3)?w3:(layer==4)?w4:w5;
    const float* g = w + ((size_t)co*Cc + ci)*9;
    float a[4][3];
#pragma unroll
    for (int j = 0; j < 3; ++j) {
        float g0 = g[j], g1 = g[3+j], g2 = g[6+j];
        a[0][j] = g0;
        a[1][j] = 0.5f*(g0 + g1 + g2);
        a[2][j] = 0.5f*(g0 - g1 + g2);
        a[3][j] = g2;
    }
    float* dst = wu + (((size_t)layer*64 + ci)*16)*64 + co;
#pragma unroll
    for (int i = 0; i < 4; ++i) {
        float a0 = a[i][0], a1 = a[i][1], a2 = a[i][2];
        dst[(i*4+0)*64] = a0;
        dst[(i*4+1)*64] = 0.5f*(a0 + a1 + a2);
        dst[(i*4+2)*64] = 0.5f*(a0 - a1 + a2);
        dst[(i*4+3)*64] = a2;
    }
}

// ---- 1x1 fuse conv (unchanged from best) ----
__global__ void __launch_bounds__(256, 2)
fuse1x1_k(const float* __restrict__ img, const float* __restrict__ gui,
          const float* __restrict__ w, const float* __restrict__ bias,
          const float* __restrict__ a_ptr, float* __restrict__ out)
{
    __shared__ ull s_wp[16*128];
    const int tid = threadIdx.x;
    const int cog = blockIdx.y;
    const int b = blockIdx.z;
    for (int e = tid; e < 16*128; e += 256) {
        int jp = e >> 7, ci = e & 127;
        int co0 = cog*32 + 2*jp;
        s_wp[e] = pack2(w[co0*128 + ci], w[(co0+1)*128 + ci]);
    }
    __syncthreads();
    const int p0 = blockIdx.x*512 + tid;
    ull acc[16][2];
#pragma unroll
    for (int jp = 0; jp < 16; ++jp) {
        int co0 = cog*32 + 2*jp;
        ull bv = pack2(bias[co0], bias[co0+1]);
        acc[jp][0] = bv; acc[jp][1] = bv;
    }
    const float* i0 = img + (size_t)b*Cc*HW + p0;
    const float* i1 = gui + (size_t)b*Cc*HW + p0;
#pragma unroll 2
    for (int ci = 0; ci < 64; ++ci) {
        const float* ic = i0 + (size_t)ci*HW;
        ull vp0 = dup2(ic[0]), vp1 = dup2(ic[256]);
#pragma unroll
        for (int jp = 0; jp < 16; ++jp) {
            ull wv = s_wp[jp*128 + ci];
            acc[jp][0] = ffma2(vp0, wv, acc[jp][0]);
            acc[jp][1] = ffma2(vp1, wv, acc[jp][1]);
        }
    }
#pragma unroll 2
    for (int ci = 0; ci < 64; ++ci) {
        const float* ic = i1 + (size_t)ci*HW;
        ull vp0 = dup2(ic[0]), vp1 = dup2(ic[256]);
#pragma unroll
        for (int jp = 0; jp < 16; ++jp) {
            ull wv = s_wp[jp*128 + 64 + ci];
            acc[jp][0] = ffma2(vp0, wv, acc[jp][0]);
            acc[jp][1] = ffma2(vp1, wv, acc[jp][1]);
        }
    }
    const float a = a_ptr[0];
#pragma unroll
    for (int jp = 0; jp < 16; ++jp) {
        int co0 = cog*32 + 2*jp;
        float* o0 = out + ((size_t)b*Cc + co0)*HW + p0;
        float* o1 = o0 + HW;
#pragma unroll
        for (int q = 0; q < 2; ++q) {
            float lo, hi; unpack2(acc[jp][q], lo, hi);
            lo = (lo >= 0.f) ? lo : a*lo;
            hi = (hi >= 0.f) ? hi : a*hi;
            o0[q*256] = lo; o1[q*256] = hi;
        }
    }
}

// ---- Winograd F(2x2,3x3) conv: CTA = 32x8 px (64 tiles) x 16 out-ch ----
#define WIN_SINF 2880                   // floats/buffer: 8ch x 10 x 36
#define WIN_SINB (WIN_SINF*4)           // 11520 B
#define WIN_SVB  (8*16*64*8)            // 65536 B (V: [ci8][u16][tile64] ull)
#define WIN_SUU  1024                   // ull/buffer: 8ci x 16u x 8 (16 co floats)
#define WIN_SUB  (WIN_SUU*8)            // 8192 B
#define WIN_SMEM (WIN_SVB + 2*WIN_SINB + 2*WIN_SUB)   // 104960

template<bool PRELU, bool RESID>
__global__ void __launch_bounds__(256, 2)
winog_k(const float* __restrict__ in,
        const float* __restrict__ wu,     // layer base: [ci][u][64co]
        const float* __restrict__ bias,
        const float* __restrict__ a_ptr,
        const float* __restrict__ resid,
        float* __restrict__ out)
{
    extern __shared__ __align__(16) char dsm[];
    ull*   sV  = (ull*)dsm;
    float* sIN = (float*)(dsm + WIN_SVB);
    ull*   sU  = (ull*)(dsm + WIN_SVB + 2*WIN_SINB);
    const unsigned sin_base = smem_u32(sIN);
    const unsigned su_base  = smem_u32(sU);

    const int tid = threadIdx.x;
    const int x0  = blockIdx.x * 32;
    const int y0  = blockIdx.y * 8;
    const int cog = blockIdx.z & 3;
    const int b   = blockIdx.z >> 2;
    const int t   = tid & 63;           // tile in CTA
    const int pg  = tid >> 6;           // 0..3 -> co_local 4pg..4pg+3
    const int ty  = t >> 4, tx = t & 15;

    ull acc[16][2];
#pragma unroll
    for (int u = 0; u < 16; ++u) { acc[u][0] = 0ULL; acc[u][1] = 0ULL; }

    const float* inb = in + (size_t)b*Cc*HW;

    unsigned hdst[11]; int hsrc[11]; unsigned hmask = 0;
#pragma unroll
    for (int q = 0; q < 11; ++q) {
        int e = tid + q*256;
        int cc  = e / 340;
        int idx = e - cc*340;
        int r   = idx / 34;
        int c2  = idx - r*34;
        int gy = y0 - 1 + r, gx = x0 - 1 + c2;
        bool ok = (e < 2720) &&
                  ((unsigned)gy < (unsigned)Hh) && ((unsigned)gx < (unsigned)Ww);
        hdst[q] = (unsigned)(cc*360 + r*36 + c2) * 4u;
        hsrc[q] = ok ? (cc*HW + gy*Ww + gx) : 0;
        if (ok) hmask |= 1u << q;
    }

    const float* wub = wu + cog*16;

    auto issue = [&](int ss) {
        const int bi = ss & 1;
        const float* srcb = inb + (size_t)(ss*8)*HW;
        unsigned sbase = sin_base + bi*WIN_SINB;
#pragma unroll
        for (int q = 0; q < 11; ++q) {
            if (q < 10 || tid < 160) {
                int ok4 = (hmask >> q) & 1;
                cp_async4(sbase + hdst[q], srcb + hsrc[q], ok4 << 2);
            }
        }
        const float* wsrc = wub + (size_t)(ss*128)*64;
        unsigned wbase = su_base + bi*WIN_SUB;
#pragma unroll
        for (int q = 0; q < 2; ++q) {
            int e = tid + q*256;            // 0..511
            int ciu = e >> 2, quad = e & 3;
            cp_async16(wbase + (unsigned)(ciu*64 + quad*16),
                       wsrc + (size_t)ciu*64 + quad*4);
        }
        cp_commit();
    };

    issue(0);

    for (int s = 0; s < 8; ++s) {
        cp_wait<0>();
        __syncthreads();
        if (s < 7) issue(s + 1);

        // input transform: V = Bt d B for 2 (ci,tile) items per thread
        const float* sif = sIN + (s & 1)*WIN_SINF;
#pragma unroll
        for (int q = 0; q < 2; ++q) {
            int item = tid + q*256;
            int tci = item >> 6;
            int tt  = item & 63;
            int tty = tt >> 4, ttx = tt & 15;
            const float* dbase = sif + tci*360 + tty*72 + ttx*2;
            ull d0a = *(const ull*)(dbase);
            ull d0b = *(const ull*)(dbase + 2);
            ull d1a = *(const ull*)(dbase + 36);
            ull d1b = *(const ull*)(dbase + 38);
            ull d2a = *(const ull*)(dbase + 72);
            ull d2b = *(const ull*)(dbase + 74);
            ull d3a = *(const ull*)(dbase + 108);
            ull d3b = *(const ull*)(dbase + 110);
            ull ta[4], tb[4];
            ta[0] = sub2(d0a, d2a); tb[0] = sub2(d0b, d2b);
            ta[1] = add2(d1a, d2a); tb[1] = add2(d1b, d2b);
            ta[2] = sub2(d2a, d1a); tb[2] = sub2(d2b, d1b);
            ta[3] = sub2(d1a, d3a); tb[3] = sub2(d1b, d3b);
            ull* dstc = sV + tci*1024 + tt;
#pragma unroll
            for (int i = 0; i < 4; ++i) {
                float c0, c1, c2, c3;
                unpack2(ta[i], c0, c1);
                unpack2(tb[i], c2, c3);
                ull* dr = dstc + i*256;
                dr[0]   = dup2(c0 - c2);
                dr[64]  = dup2(c1 + c2);
                dr[128] = dup2(c2 - c1);
                dr[192] = dup2(c1 - c3);
            }
        }
        __syncthreads();

        // MAC phase
        const ull* su = sU + (s & 1)*WIN_SUU;
        const ull* Vt = sV + t;
#pragma unroll
        for (int ci = 0; ci < 8; ++ci) {
            const ull* vrow = Vt + ci*1024;
            const ull* urow = su + ci*128 + 2*pg;
#pragma unroll
            for (int u = 0; u < 16; ++u) {
                ull vp = vrow[u*64];
                ulonglong2 U2 = *(const ulonglong2*)(urow + u*8);
                acc[u][0] = ffma2(vp, U2.x, acc[u][0]);
                acc[u][1] = ffma2(vp, U2.y, acc[u][1]);
            }
        }
    }

    // epilogue: Y = At M A, +bias, PReLU, residual
    float ap = 0.f;
    if (PRELU) ap = a_ptr[0];
    const int px = x0 + 2*tx;
#pragma unroll
    for (int p = 0; p < 2; ++p) {
        const int co0 = cog*16 + pg*4 + 2*p;
        ull q0[4], q1[4];
#pragma unroll
        for (int j = 0; j < 4; ++j) {
            q0[j] = add2(add2(acc[j][p], acc[4+j][p]), acc[8+j][p]);
            q1[j] = sub2(sub2(acc[4+j][p], acc[8+j][p]), acc[12+j][p]);
        }
        ull bv = pack2(bias[co0], bias[co0+1]);
        ull y00 = add2(add2(add2(q0[0], q0[1]), q0[2]), bv);
        ull y01 = add2(sub2(sub2(q0[1], q0[2]), q0[3]), bv);
        ull y10 = add2(add2(add2(q1[0], q1[1]), q1[2]), bv);
        ull y11 = add2(sub2(sub2(q1[1], q1[2]), q1[3]), bv);

        float v[2][2][2];
        unpack2(y00, v[0][0][0], v[0][0][1]);
        unpack2(y01, v[0][1][0], v[0][1][1]);
        unpack2(y10, v[1][0][0], v[1][0][1]);
        unpack2(y11, v[1][1][0], v[1][1][1]);
        if (PRELU) {
#pragma unroll
            for (int i = 0; i < 2; ++i)
#pragma unroll
                for (int j = 0; j < 2; ++j)
#pragma unroll
                    for (int l = 0; l < 2; ++l) {
                        float z = v[i][j][l];
                        v[i][j][l] = (z >= 0.f) ? z : ap*z;
                    }
        }
#pragma unroll
        for (int l = 0; l < 2; ++l) {
            const int co = co0 + l;
#pragma unroll
            for (int i = 0; i < 2; ++i) {
                const int py = y0 + 2*ty + i;
                size_t o = ((size_t)(b*Cc + co)*Hh + py)*Ww + px;
                float2 val = make_float2(v[i][0][l], v[i][1][l]);
                if (RESID) {
                    float2 rr = *(const float2*)(resid + o);
                    val.x += rr.x; val.y += rr.y;
                }
                *(float2*)(out + o) = val;
            }
        }
    }
}

// ---- fused kg5 1x1 (64->576) + dynamic JBF (unchanged from best) ----
#define KGJ_SMEM (288*64*4 + 288*4)

__global__ void __launch_bounds__(256, 2)
kgjbf_k(const float* __restrict__ y4, const float* __restrict__ w5,
        const float* __restrict__ b5, const float* __restrict__ img,
        float* __restrict__ out)
{
    extern __shared__ float smem[];
    float* s_w5 = smem;
    float* s_b5 = smem + 288*64;
    const int tid = threadIdx.x;
    const int ci0 = blockIdx.y*32;
    const int b = blockIdx.z;
    const int p = blockIdx.x * 256 + tid;
    const int y = p >> 8;
    const int x = p & 255;
    {
        float4* dst = (float4*)s_w5;
        for (int e = tid; e < 288*16; e += 256) {
            int row = e >> 4, q = e & 15;
            int f = ((row >> 5) << 6) + ci0 + (row & 31);
            dst[e] = ((const float4*)(w5 + (size_t)f*64))[q];
        }
        for (int e = tid; e < 288; e += 256)
            s_b5[e] = b5[((e >> 5) << 6) + ci0 + (e & 31)];
    }
    __syncthreads();
    ull yp[32];
    {
        const float* yb = y4 + (size_t)b*Cc*HW + p;
#pragma unroll
        for (int c2 = 0; c2 < 32; ++c2)
            yp[c2] = pack2(yb[(size_t)(2*c2)*HW], yb[(size_t)(2*c2+1)*HW]);
    }
    const float* ib = img + (size_t)b*Cc*HW;
    float* ob = out + ((size_t)b*Cc + ci0)*HW + p;
    for (int j = 0; j < 32; ++j) {
        const int ci = ci0 + j;
        float acc = 0.f;
#pragma unroll
        for (int kk = 0; kk < 9; ++kk) {
            const int f = kk*64 + ci;
            const int row = kk*32 + j;
            const ulonglong2* wrow = (const ulonglong2*)(s_w5 + row*64);
            ull p0 = 0ULL, p1 = 0ULL, p2 = 0ULL, p3 = 0ULL;
#pragma unroll
            for (int c4 = 0; c4 < 16; c4 += 4) {
                ulonglong2 wv0 = wrow[c4  ];
                ulonglong2 wv1 = wrow[c4+1];
                ulonglong2 wv2 = wrow[c4+2];
                ulonglong2 wv3 = wrow[c4+3];
                p0 = ffma2(yp[2*c4  ], wv0.x, p0);
                p1 = ffma2(yp[2*c4+1], wv0.y, p1);
                p2 = ffma2(yp[2*c4+2], wv1.x, p2);
                p3 = ffma2(yp[2*c4+3], wv1.y, p3);
                p0 = ffma2(yp[2*c4+4], wv2.x, p0);
                p1 = ffma2(yp[2*c4+5], wv2.y, p1);
                p2 = ffma2(yp[2*c4+6], wv3.x, p2);
                p3 = ffma2(yp[2*c4+7], wv3.y, p3);
            }
            p0 = add2(p0, p1); p2 = add2(p2, p3); p0 = add2(p0, p2);
            float lo, hi; unpack2(p0, lo, hi);
            float bik = lo + hi + s_b5[row];
            int ch  = f / 9;
            int tap = f - ch*9;
            int dy  = tap / 3 - 1;
            int dx  = tap - (tap/3)*3 - 1;
            int yy = y + dy, xx = x + dx;
            float iv = 0.f;
            if ((unsigned)yy < (unsigned)Hh && (unsigned)xx < (unsigned)Ww)
                iv = ib[(size_t)ch*HW + yy*Ww + xx];
            acc = fmaf(bik, iv, acc);
        }
        ob[(size_t)j*HW] = acc;
    }
}

// ---------------------------------------------------------------------------
extern "C" void kernel_launch(void* const* d_in, const int* in_sizes, int n_in,
                              void* d_out, int out_size)
{
    const float* image   = (const float*)d_in[0];
    const float* guidance= (const float*)d_in[1];
    const float* tensor_w= (const float*)d_in[2];
    const float* tensor_b= (const float*)d_in[3];
    const float* a_jbf   = (const float*)d_in[4];
    const float* kg_w1   = (const float*)d_in[5];
    const float* kg_b1   = (const float*)d_in[6];
    const float* kg_w2   = (const float*)d_in[7];
    const float* kg_b2   = (const float*)d_in[8];
    const float* kg_w3   = (const float*)d_in[9];
    const float* kg_b3   = (const float*)d_in[10];
    const float* kg_w4   = (const float*)d_in[11];
    const float* kg_b4   = (const float*)d_in[12];
    const float* kg_w5   = (const float*)d_in[13];
    const float* kg_b5   = (const float*)d_in[14];
    const float* a_kg    = (const float*)d_in[15];
    const float* jbf_w1  = (const float*)d_in[16];
    const float* jbf_b1  = (const float*)d_in[17];
    const float* jbf_w2  = (const float*)d_in[18];
    const float* jbf_b2  = (const float*)d_in[19];
    float* out = (float*)d_out;

    float *A, *Bb, *WU;
    cudaGetSymbolAddress((void**)&A,  g_A);
    cudaGetSymbolAddress((void**)&Bb, g_B);
    cudaGetSymbolAddress((void**)&WU, g_WU);

    static bool attr_set = false;
    if (!attr_set) {
        cudaFuncSetAttribute(kgjbf_k, cudaFuncAttributeMaxDynamicSharedMemorySize, KGJ_SMEM);
        cudaFuncSetAttribute(winog_k<true,false>,
                             cudaFuncAttributeMaxDynamicSharedMemorySize, WIN_SMEM);
        cudaFuncSetAttribute(winog_k<false,true>,
                             cudaFuncAttributeMaxDynamicSharedMemorySize, WIN_SMEM);
        attr_set = true;
    }

    dim3 blk(256);
    dim3 gf(HW/512, 2, Bn);
    dim3 gw(Ww/32, Hh/8, 4*Bn);
    dim3 gj(HW/256, 2, Bn);

    pack_wu_k<<<96, blk>>>(kg_w1, kg_w2, kg_w3, kg_w4, jbf_w1, jbf_w2, WU);

    fuse1x1_k<<<gf, blk>>>(image, guidance, tensor_w, tensor_b, a_jbf, A);
    winog_k<true,false><<<gw, blk, WIN_SMEM>>>(A,  WU + 0*65536, kg_b1, a_kg, nullptr, Bb);
    winog_k<true,false><<<gw, blk, WIN_SMEM>>>(Bb, WU + 1*65536, kg_b2, a_kg, nullptr, A);
    winog_k<true,false><<<gw, blk, WIN_SMEM>>>(A,  WU + 2*65536, kg_b3, a_kg, nullptr, Bb);
    winog_k<true,false><<<gw, blk, WIN_SMEM>>>(Bb, WU + 3*65536, kg_b4, a_kg, nullptr, A);
    kgjbf_k<<<gj, blk, KGJ_SMEM>>>(A, kg_w5, kg_b5, image, Bb);
    winog_k<true,false><<<gw, blk, WIN_SMEM>>>(Bb, WU + 4*65536, jbf_b1, a_jbf, nullptr, A);
    winog_k<false,true><<<gw, blk, WIN_SMEM>>>(A,  WU + 5*65536, jbf_b2, nullptr, image, out);
}

// round 12
// speedup vs baseline: 1.4921x; 1.4921x over previous
#include <cuda_runtime.h>
#include <cuda_bf16.h>
#include <cstddef>

#define Bn 2
#define Cc 64
#define Hh 256
#define Ww 256
#define HW (Hh*Ww)

typedef unsigned long long ull;

__device__ float g_A[(size_t)Bn*Cc*HW];
__device__ float g_B[(size_t)Bn*Cc*HW];
__device__ ull   g_WP[6*64*9*32];

__device__ __forceinline__ ull pack2(float lo, float hi) {
    ull r; asm("mov.b64 %0, {%1, %2};" : "=l"(r) : "f"(lo), "f"(hi)); return r;
}
__device__ __forceinline__ ull dup2(float v) {
    ull r; asm("mov.b64 %0, {%1, %1};" : "=l"(r) : "f"(v)); return r;
}
__device__ __forceinline__ void unpack2(ull v, float& lo, float& hi) {
    asm("mov.b64 {%0, %1}, %2;" : "=f"(lo), "=f"(hi) : "l"(v));
}
__device__ __forceinline__ ull ffma2(ull a, ull b, ull c) {
    ull d; asm("fma.rn.f32x2 %0, %1, %2, %3;" : "=l"(d) : "l"(a), "l"(b), "l"(c)); return d;
}
__device__ __forceinline__ ull add2(ull a, ull b) {
    ull d; asm("add.rn.f32x2 %0, %1, %2;" : "=l"(d) : "l"(a), "l"(b)); return d;
}
__device__ __forceinline__ unsigned smem_u32(const void* p) {
    unsigned a;
    asm("{ .reg .u64 t; cvta.to.shared.u64 t, %1; cvt.u32.u64 %0, t; }" : "=r"(a) : "l"(p));
    return a;
}
__device__ __forceinline__ void cp_async4(unsigned dst, const void* src, int sz) {
    asm volatile("cp.async.ca.shared.global [%0], [%1], 4, %2;" :: "r"(dst), "l"(src), "r"(sz) : "memory");
}
__device__ __forceinline__ void cp_async16(unsigned dst, const void* src) {
    asm volatile("cp.async.cg.shared.global [%0], [%1], 16;" :: "r"(dst), "l"(src) : "memory");
}
__device__ __forceinline__ void cp_commit() { asm volatile("cp.async.commit_group;" ::: "memory"); }
template<int N> __device__ __forceinline__ void cp_wait() {
    asm volatile("cp.async.wait_group %0;" :: "n"(N) : "memory");
}

// ---- one-shot weight packer: wp[layer][ci][k][pr] ----
__global__ void pack_w_k(const float* __restrict__ w0, const float* __restrict__ w1,
                         const float* __restrict__ w2, const float* __restrict__ w3,
                         const float* __restrict__ w4, const float* __restrict__ w5,
                         ull* __restrict__ wp)
{
    int idx = blockIdx.x*256 + threadIdx.x;
    if (idx >= 110592) return;
    int layer = idx / 18432; int r = idx - layer*18432;
    int ci  = r / 288;       r -= ci*288;
    int k   = r / 32;        int pr = r - k*32;
    const float* w = (layer==0)?w0:(layer==1)?w1:(layer==2)?w2:
                     (layer==3)?w3:(layer==4)?w4:w5;
    int co0 = pr*2;
    wp[idx] = pack2(w[(co0*Cc + ci)*9 + k], w[((co0+1)*Cc + ci)*9 + k]);
}

// ---- 1x1 fuse conv ----
__global__ void __launch_bounds__(256, 2)
fuse1x1_k(const float* __restrict__ img, const float* __restrict__ gui,
          const float* __restrict__ w, const float* __restrict__ bias,
          const float* __restrict__ a_ptr, float* __restrict__ out)
{
    __shared__ ull s_wp[16*128];
    const int tid = threadIdx.x;
    const int cog = blockIdx.y;
    const int b = blockIdx.z;
    for (int e = tid; e < 16*128; e += 256) {
        int jp = e >> 7, ci = e & 127;
        int co0 = cog*32 + 2*jp;
        s_wp[e] = pack2(w[co0*128 + ci], w[(co0+1)*128 + ci]);
    }
    __syncthreads();
    const int p0 = blockIdx.x*512 + tid;
    ull acc[16][2];
#pragma unroll
    for (int jp = 0; jp < 16; ++jp) {
        int co0 = cog*32 + 2*jp;
        ull bv = pack2(bias[co0], bias[co0+1]);
        acc[jp][0] = bv; acc[jp][1] = bv;
    }
    const float* i0 = img + (size_t)b*Cc*HW + p0;
    const float* i1 = gui + (size_t)b*Cc*HW + p0;
#pragma unroll 2
    for (int ci = 0; ci < 64; ++ci) {
        const float* ic = i0 + (size_t)ci*HW;
        ull vp0 = dup2(ic[0]), vp1 = dup2(ic[256]);
#pragma unroll
        for (int jp = 0; jp < 16; ++jp) {
            ull wv = s_wp[jp*128 + ci];
            acc[jp][0] = ffma2(vp0, wv, acc[jp][0]);
            acc[jp][1] = ffma2(vp1, wv, acc[jp][1]);
        }
    }
#pragma unroll 2
    for (int ci = 0; ci < 64; ++ci) {
        const float* ic = i1 + (size_t)ci*HW;
        ull vp0 = dup2(ic[0]), vp1 = dup2(ic[256]);
#pragma unroll
        for (int jp = 0; jp < 16; ++jp) {
            ull wv = s_wp[jp*128 + 64 + ci];
            acc[jp][0] = ffma2(vp0, wv, acc[jp][0]);
            acc[jp][1] = ffma2(vp1, wv, acc[jp][1]);
        }
    }
    const float a = a_ptr[0];
#pragma unroll
    for (int jp = 0; jp < 16; ++jp) {
        int co0 = cog*32 + 2*jp;
        float* o0 = out + ((size_t)b*Cc + co0)*HW + p0;
        float* o1 = o0 + HW;
#pragma unroll
        for (int q = 0; q < 2; ++q) {
            float lo, hi; unpack2(acc[jp][q], lo, hi);
            lo = (lo >= 0.f) ? lo : a*lo;
            hi = (hi >= 0.f) ? hi : a*hi;
            o0[q*256] = lo; o1[q*256] = hi;
        }
    }
}

// ---- direct 3x3 conv (R9 proven version) ----
#define SIN_F   2800
#define SW_U    2304
#define SIN_BYTES (SIN_F*4)
#define SW_BYTES  (SW_U*8)
#define CONV_SMEM (3*(SIN_BYTES + SW_BYTES))

template<bool PRELU, bool RESID>
__global__ void __launch_bounds__(256, 2)
conv3x3_k(const float* __restrict__ in,
          const ull*   __restrict__ wp,
          const float* __restrict__ bias,
          const float* __restrict__ a_ptr,
          const float* __restrict__ resid,
          float* __restrict__ out)
{
    extern __shared__ __align__(16) char dyn_smem[];
    float* sin_f = (float*)dyn_smem;
    ull*   sw_u  = (ull*)(dyn_smem + 3*SIN_BYTES);
    const unsigned sin_base = smem_u32(sin_f);
    const unsigned sw_base  = smem_u32(sw_u);

    const int tid = threadIdx.x;
    const int x0  = blockIdx.x * 32;
    const int y0  = blockIdx.y * 8;
    const int b   = blockIdx.z;
    const int wg  = tid >> 5;
    const int lane = tid & 31;
    const int rp  = lane >> 3;
    const int xs  = (lane & 7) * 4;
    const int co0 = wg*8;

    ull acc[4][2][4];
#pragma unroll
    for (int j = 0; j < 4; ++j) {
        ull bv = pack2(bias[co0 + 2*j], bias[co0 + 2*j + 1]);
#pragma unroll
        for (int L = 0; L < 2; ++L)
#pragma unroll
            for (int px = 0; px < 4; ++px) acc[j][L][px] = bv;
    }

    const float* inb = in + (size_t)b*Cc*HW;

    unsigned hdst[11]; int hsrc[11]; unsigned hmask = 0;
#pragma unroll
    for (int q = 0; q < 11; ++q) {
        int e = tid + q*256;
        int cc  = e / 340;
        int idx = e - cc*340;
        int r   = idx / 34;
        int c2  = idx - r*34;
        int gy = y0 - 1 + r, gx = x0 - 1 + c2;
        bool ok = (e < 2720) &&
                  ((unsigned)gy < (unsigned)Hh) && ((unsigned)gx < (unsigned)Ww);
        hdst[q] = (unsigned)(cc*350 + r*35 + c2) * 4u;
        hsrc[q] = ok ? (cc*HW + gy*Ww + gx) : 0;
        if (ok) hmask |= 1u << q;
    }

    auto issue = [&](int st, int cb) {
        const float* srcb = inb + (size_t)cb*HW;
        unsigned sbase = sin_base + st*SIN_BYTES;
#pragma unroll
        for (int q = 0; q < 11; ++q) {
            if (q < 10 || tid < 160) {
                int ok4 = (hmask >> q) & 1;
                cp_async4(sbase + hdst[q], srcb + hsrc[q], ok4 << 2);
            }
        }
        const ull* wsrc = wp + (size_t)cb*288;
        unsigned wbase = sw_base + st*SW_BYTES;
#pragma unroll
        for (int q = 0; q < 5; ++q) {
            int e = tid + q*256;
            if (q < 4 || tid < 128) {
                cp_async16(wbase + (unsigned)e*16u, wsrc + 2*e);
            }
        }
        cp_commit();
    };

    issue(0, 0);
    issue(1, 8);

    for (int s = 0; s < 8; ++s) {
        if (s >= 6) cp_wait<0>(); else cp_wait<1>();
        __syncthreads();
        if (s + 2 < 8) issue((s + 2) % 3, (s + 2) * 8);

        const int st = s % 3;
        const float* sif = sin_f + st*SIN_F;
        const ull*   swu = sw_u  + st*SW_U;
#pragma unroll
        for (int cc = 0; cc < 8; ++cc) {
#pragma unroll
            for (int r_in = 0; r_in < 4; ++r_in) {
                const int h = 2*rp + r_in;
                ull tp[6];
#pragma unroll
                for (int c = 0; c < 6; ++c) {
                    float t = sif[cc*350 + h*35 + xs + c];
                    tp[c] = dup2(t);
                }
#pragma unroll
                for (int L = 0; L < 2; ++L) {
                    if (r_in - L < 0 || r_in - L > 2) continue;
                    const int dy = r_in - L;
#pragma unroll
                    for (int dx = 0; dx < 3; ++dx) {
                        const int k = dy*3 + dx;
                        ulonglong2 w01 = *(const ulonglong2*)&swu[cc*288 + k*32 + wg*4];
                        ulonglong2 w23 = *(const ulonglong2*)&swu[cc*288 + k*32 + wg*4 + 2];
#pragma unroll
                        for (int px = 0; px < 4; ++px) {
                            ull a = tp[px + dx];
                            acc[0][L][px] = ffma2(a, w01.x, acc[0][L][px]);
                            acc[1][L][px] = ffma2(a, w01.y, acc[1][L][px]);
                            acc[2][L][px] = ffma2(a, w23.x, acc[2][L][px]);
                            acc[3][L][px] = ffma2(a, w23.y, acc[3][L][px]);
                        }
                    }
                }
            }
        }
    }

    float a = 0.f;
    if (PRELU) a = a_ptr[0];
    const int x = x0 + xs;
#pragma unroll
    for (int j = 0; j < 4; ++j) {
#pragma unroll
        for (int L = 0; L < 2; ++L) {
            const int y = y0 + 2*rp + L;
            float v0[4], v1[4];
#pragma unroll
            for (int px = 0; px < 4; ++px) {
                unpack2(acc[j][L][px], v0[px], v1[px]);
                if (PRELU) {
                    v0[px] = (v0[px] >= 0.f) ? v0[px] : a*v0[px];
                    v1[px] = (v1[px] >= 0.f) ? v1[px] : a*v1[px];
                }
            }
            size_t o0 = ((size_t)(b*Cc + co0 + 2*j)*Hh + y)*Ww + x;
            size_t o1 = o0 + (size_t)HW;
            float4 a0 = make_float4(v0[0], v0[1], v0[2], v0[3]);
            float4 b0 = make_float4(v1[0], v1[1], v1[2], v1[3]);
            if (RESID) {
                float4 r0 = *(const float4*)(resid + o0);
                float4 r1 = *(const float4*)(resid + o1);
                a0.x += r0.x; a0.y += r0.y; a0.z += r0.z; a0.w += r0.w;
                b0.x += r1.x; b0.y += r1.y; b0.z += r1.z; b0.w += r1.w;
            }
            *(float4*)(out + o0) = a0;
            *(float4*)(out + o1) = b0;
        }
    }
}

// ---- fused kg5 + dynamic JBF, ci-split, gather-hoisted ----
#define KGJ_SMEM (288*64*4 + 288*4)

__global__ void __launch_bounds__(256, 2)
kgjbf_k(const float* __restrict__ y4, const float* __restrict__ w5,
        const float* __restrict__ b5, const float* __restrict__ img,
        float* __restrict__ out)
{
    extern __shared__ float smem[];
    float* s_w5 = smem;
    float* s_b5 = smem + 288*64;
    const int tid = threadIdx.x;
    const int ci0 = blockIdx.y*32;
    const int b = blockIdx.z;
    const int p = blockIdx.x * 256 + tid;
    const int y = p >> 8;
    const int x = p & 255;
    {
        float4* dst = (float4*)s_w5;
        for (int e = tid; e < 288*16; e += 256) {
            int row = e >> 4, q = e & 15;
            int f = ((row >> 5) << 6) + ci0 + (row & 31);
            dst[e] = ((const float4*)(w5 + (size_t)f*64))[q];
        }
        for (int e = tid; e < 288; e += 256)
            s_b5[e] = b5[((e >> 5) << 6) + ci0 + (e & 31)];
    }
    __syncthreads();
    ull yp[32];
    {
        const float* yb = y4 + (size_t)b*Cc*HW + p;
#pragma unroll
        for (int c2 = 0; c2 < 32; ++c2)
            yp[c2] = pack2(yb[(size_t)(2*c2)*HW], yb[(size_t)(2*c2+1)*HW]);
    }
    const float* ib = img + (size_t)b*Cc*HW;
    float* ob = out + ((size_t)b*Cc + ci0)*HW + p;

    // hoisted spatial tap offsets + in-bounds mask (t = tap index 0..8)
    int off[9]; unsigned okm = 0;
#pragma unroll
    for (int t = 0; t < 9; ++t) {
        int dy = t/3 - 1, dx = t - (t/3)*3 - 1;
        int yy = y + dy, xx = x + dx;
        off[t] = yy*Ww + xx;
        if ((unsigned)yy < (unsigned)Hh && (unsigned)xx < (unsigned)Ww) okm |= 1u << t;
    }
    const int tap00 = ci0 % 9;   // tap for (j=0, kk=0); ci0 is 0 or 32

    for (int j = 0; j < 32; ++j) {
        const int ci = ci0 + j;
        int tap0 = tap00 + j; tap0 -= (tap0 >= 9) ? 9 : 0; tap0 -= (tap0 >= 9) ? 9 : 0;
        // for j up to 31, tap00+j < 41 -> subtracting 9 up to 4 times needed; do mod once:
        tap0 = (tap00 + j) % 9;
        float acc = 0.f;
#pragma unroll
        for (int t = 0; t < 9; ++t) {        // t = tap (compile-time index)
            int kk = t - tap0; kk += (kk < 0) ? 9 : 0;
            const int row = kk*32 + j;
            const ulonglong2* wrow = (const ulonglong2*)(s_w5 + row*64);
            ull p0 = 0ULL, p1 = 0ULL, p2 = 0ULL, p3 = 0ULL;
#pragma unroll
            for (int c4 = 0; c4 < 16; c4 += 4) {
                ulonglong2 wv0 = wrow[c4  ];
                ulonglong2 wv1 = wrow[c4+1];
                ulonglong2 wv2 = wrow[c4+2];
                ulonglong2 wv3 = wrow[c4+3];
                p0 = ffma2(yp[2*c4  ], wv0.x, p0);
                p1 = ffma2(yp[2*c4+1], wv0.y, p1);
                p2 = ffma2(yp[2*c4+2], wv1.x, p2);
                p3 = ffma2(yp[2*c4+3], wv1.y, p3);
                p0 = ffma2(yp[2*c4+4], wv2.x, p0);
                p1 = ffma2(yp[2*c4+5], wv2.y, p1);
                p2 = ffma2(yp[2*c4+6], wv3.x, p2);
                p3 = ffma2(yp[2*c4+7], wv3.y, p3);
            }
            p0 = add2(p0, p1); p2 = add2(p2, p3); p0 = add2(p0, p2);
            float lo, hi; unpack2(p0, lo, hi);
            float bik = lo + hi + s_b5[row];
            // ch = (64*kk + ci - t)/9 exactly; 9^{-1} mod 2^32 = 0x38E38E39
            unsigned ch = (unsigned)(64*kk + ci - t) * 0x38E38E39u;
            float iv = 0.f;
            if ((okm >> t) & 1) iv = ib[(size_t)ch*HW + off[t]];
            acc = fmaf(bik, iv, acc);
        }
        ob[(size_t)j*HW] = acc;
    }
}

// ---------------------------------------------------------------------------
extern "C" void kernel_launch(void* const* d_in, const int* in_sizes, int n_in,
                              void* d_out, int out_size)
{
    const float* image   = (const float*)d_in[0];
    const float* guidance= (const float*)d_in[1];
    const float* tensor_w= (const float*)d_in[2];
    const float* tensor_b= (const float*)d_in[3];
    const float* a_jbf   = (const float*)d_in[4];
    const float* kg_w1   = (const float*)d_in[5];
    const float* kg_b1   = (const float*)d_in[6];
    const float* kg_w2   = (const float*)d_in[7];
    const float* kg_b2   = (const float*)d_in[8];
    const float* kg_w3   = (const float*)d_in[9];
    const float* kg_b3   = (const float*)d_in[10];
    const float* kg_w4   = (const float*)d_in[11];
    const float* kg_b4   = (const float*)d_in[12];
    const float* kg_w5   = (const float*)d_in[13];
    const float* kg_b5   = (const float*)d_in[14];
    const float* a_kg    = (const float*)d_in[15];
    const float* jbf_w1  = (const float*)d_in[16];
    const float* jbf_b1  = (const float*)d_in[17];
    const float* jbf_w2  = (const float*)d_in[18];
    const float* jbf_b2  = (const float*)d_in[19];
    float* out = (float*)d_out;

    float *A, *Bb;
    ull* WP;
    cudaGetSymbolAddress((void**)&A,  g_A);
    cudaGetSymbolAddress((void**)&Bb, g_B);
    cudaGetSymbolAddress((void**)&WP, g_WP);

    static bool attr_set = false;
    if (!attr_set) {
        cudaFuncSetAttribute(kgjbf_k, cudaFuncAttributeMaxDynamicSharedMemorySize, KGJ_SMEM);
        cudaFuncSetAttribute(conv3x3_k<true,false>,
                             cudaFuncAttributeMaxDynamicSharedMemorySize, CONV_SMEM);
        cudaFuncSetAttribute(conv3x3_k<false,true>,
                             cudaFuncAttributeMaxDynamicSharedMemorySize, CONV_SMEM);
        attr_set = true;
    }

    dim3 blk(256);
    dim3 gf(HW/512, 2, Bn);
    dim3 g3(Ww/32, Hh/8, Bn);
    dim3 gj(HW/256, 2, Bn);

    pack_w_k<<<(110592 + 255)/256, blk>>>(kg_w1, kg_w2, kg_w3, kg_w4, jbf_w1, jbf_w2, WP);

    fuse1x1_k<<<gf, blk>>>(image, guidance, tensor_w, tensor_b, a_jbf, A);
    conv3x3_k<true,false><<<g3, blk, CONV_SMEM>>>(A,  WP + 0*18432, kg_b1, a_kg, nullptr, Bb);
    conv3x3_k<true,false><<<g3, blk, CONV_SMEM>>>(Bb, WP + 1*18432, kg_b2, a_kg, nullptr, A);
    conv3x3_k<true,false><<<g3, blk, CONV_SMEM>>>(A,  WP + 2*18432, kg_b3, a_kg, nullptr, Bb);
    conv3x3_k<true,false><<<g3, blk, CONV_SMEM>>>(Bb, WP + 3*18432, kg_b4, a_kg, nullptr, A);
    kgjbf_k<<<gj, blk, KGJ_SMEM>>>(A, kg_w5, kg_b5, image, Bb);
    conv3x3_k<true,false><<<g3, blk, CONV_SMEM>>>(Bb, WP + 4*18432, jbf_b1, a_jbf, nullptr, A);
    conv3x3_k<false,true><<<g3, blk, CONV_SMEM>>>(A,  WP + 5*18432, jbf_b2, nullptr, image, out);
}

// round 13
// speedup vs baseline: 1.5531x; 1.0409x over previous
#include <cuda_runtime.h>
#include <cuda_bf16.h>
#include <cstddef>

#define Bn 2
#define Cc 64
#define Hh 256
#define Ww 256
#define HW (Hh*Ww)

typedef unsigned long long ull;

__device__ float g_A[(size_t)Bn*Cc*HW];
__device__ float g_B[(size_t)Bn*Cc*HW];
__device__ ull   g_WP[6*64*9*32];

__device__ __forceinline__ ull pack2(float lo, float hi) {
    ull r; asm("mov.b64 %0, {%1, %2};" : "=l"(r) : "f"(lo), "f"(hi)); return r;
}
__device__ __forceinline__ ull dup2(float v) {
    ull r; asm("mov.b64 %0, {%1, %1};" : "=l"(r) : "f"(v)); return r;
}
__device__ __forceinline__ void unpack2(ull v, float& lo, float& hi) {
    asm("mov.b64 {%0, %1}, %2;" : "=f"(lo), "=f"(hi) : "l"(v));
}
__device__ __forceinline__ ull ffma2(ull a, ull b, ull c) {
    ull d; asm("fma.rn.f32x2 %0, %1, %2, %3;" : "=l"(d) : "l"(a), "l"(b), "l"(c)); return d;
}
__device__ __forceinline__ ull add2(ull a, ull b) {
    ull d; asm("add.rn.f32x2 %0, %1, %2;" : "=l"(d) : "l"(a), "l"(b)); return d;
}
__device__ __forceinline__ unsigned smem_u32(const void* p) {
    unsigned a;
    asm("{ .reg .u64 t; cvta.to.shared.u64 t, %1; cvt.u32.u64 %0, t; }" : "=r"(a) : "l"(p));
    return a;
}
__device__ __forceinline__ void cp_async4(unsigned dst, const void* src, int sz) {
    asm volatile("cp.async.ca.shared.global [%0], [%1], 4, %2;" :: "r"(dst), "l"(src), "r"(sz) : "memory");
}
__device__ __forceinline__ void cp_async16(unsigned dst, const void* src) {
    asm volatile("cp.async.cg.shared.global [%0], [%1], 16;" :: "r"(dst), "l"(src) : "memory");
}
__device__ __forceinline__ void cp_commit() { asm volatile("cp.async.commit_group;" ::: "memory"); }
template<int N> __device__ __forceinline__ void cp_wait() {
    asm volatile("cp.async.wait_group %0;" :: "n"(N) : "memory");
}

// ---- one-shot weight packer: wp[layer][ci][k][pr] ----
__global__ void pack_w_k(const float* __restrict__ w0, const float* __restrict__ w1,
                         const float* __restrict__ w2, const float* __restrict__ w3,
                         const float* __restrict__ w4, const float* __restrict__ w5,
                         ull* __restrict__ wp)
{
    int idx = blockIdx.x*256 + threadIdx.x;
    if (idx >= 110592) return;
    int layer = idx / 18432; int r = idx - layer*18432;
    int ci  = r / 288;       r -= ci*288;
    int k   = r / 32;        int pr = r - k*32;
    const float* w = (layer==0)?w0:(layer==1)?w1:(layer==2)?w2:
                     (layer==3)?w3:(layer==4)?w4:w5;
    int co0 = pr*2;
    wp[idx] = pack2(w[(co0*Cc + ci)*9 + k], w[((co0+1)*Cc + ci)*9 + k]);
}

// ---- 1x1 fuse conv (unchanged) ----
__global__ void __launch_bounds__(256, 2)
fuse1x1_k(const float* __restrict__ img, const float* __restrict__ gui,
          const float* __restrict__ w, const float* __restrict__ bias,
          const float* __restrict__ a_ptr, float* __restrict__ out)
{
    __shared__ ull s_wp[16*128];
    const int tid = threadIdx.x;
    const int cog = blockIdx.y;
    const int b = blockIdx.z;
    for (int e = tid; e < 16*128; e += 256) {
        int jp = e >> 7, ci = e & 127;
        int co0 = cog*32 + 2*jp;
        s_wp[e] = pack2(w[co0*128 + ci], w[(co0+1)*128 + ci]);
    }
    __syncthreads();
    const int p0 = blockIdx.x*512 + tid;
    ull acc[16][2];
#pragma unroll
    for (int jp = 0; jp < 16; ++jp) {
        int co0 = cog*32 + 2*jp;
        ull bv = pack2(bias[co0], bias[co0+1]);
        acc[jp][0] = bv; acc[jp][1] = bv;
    }
    const float* i0 = img + (size_t)b*Cc*HW + p0;
    const float* i1 = gui + (size_t)b*Cc*HW + p0;
#pragma unroll 2
    for (int ci = 0; ci < 64; ++ci) {
        const float* ic = i0 + (size_t)ci*HW;
        ull vp0 = dup2(ic[0]), vp1 = dup2(ic[256]);
#pragma unroll
        for (int jp = 0; jp < 16; ++jp) {
            ull wv = s_wp[jp*128 + ci];
            acc[jp][0] = ffma2(vp0, wv, acc[jp][0]);
            acc[jp][1] = ffma2(vp1, wv, acc[jp][1]);
        }
    }
#pragma unroll 2
    for (int ci = 0; ci < 64; ++ci) {
        const float* ic = i1 + (size_t)ci*HW;
        ull vp0 = dup2(ic[0]), vp1 = dup2(ic[256]);
#pragma unroll
        for (int jp = 0; jp < 16; ++jp) {
            ull wv = s_wp[jp*128 + 64 + ci];
            acc[jp][0] = ffma2(vp0, wv, acc[jp][0]);
            acc[jp][1] = ffma2(vp1, wv, acc[jp][1]);
        }
    }
    const float a = a_ptr[0];
#pragma unroll
    for (int jp = 0; jp < 16; ++jp) {
        int co0 = cog*32 + 2*jp;
        float* o0 = out + ((size_t)b*Cc + co0)*HW + p0;
        float* o1 = o0 + HW;
#pragma unroll
        for (int q = 0; q < 2; ++q) {
            float lo, hi; unpack2(acc[jp][q], lo, hi);
            lo = (lo >= 0.f) ? lo : a*lo;
            hi = (hi >= 0.f) ? hi : a*hi;
            o0[q*256] = lo; o1[q*256] = hi;
        }
    }
}

// ---- direct 3x3 conv: 3 CTAs/SM, double-buffered, 32 co per CTA ----
// grid (8, 32, 2*B); block 256. Thread: 2 rows x 4 px x 4 out-ch (2 pairs).
#define SIN_F   2800                    // 8ch x 350
#define SW_U    1152                    // 8ch x 9k x 16 pairs
#define SIN_BYTES (SIN_F*4)             // 11200
#define SW_BYTES  (SW_U*8)              // 9216
#define CONV_SMEM (2*(SIN_BYTES + SW_BYTES))   // 40832

template<bool PRELU, bool RESID>
__global__ void __launch_bounds__(256, 3)
conv3x3_k(const float* __restrict__ in,
          const ull*   __restrict__ wp,    // [ci][k][32 pairs]
          const float* __restrict__ bias,
          const float* __restrict__ a_ptr,
          const float* __restrict__ resid,
          float* __restrict__ out)
{
    extern __shared__ __align__(16) char dyn_smem[];
    float* sin_f = (float*)dyn_smem;                       // 2 x 2800 f
    ull*   sw_u  = (ull*)(dyn_smem + 2*SIN_BYTES);         // 2 x 1152 ull
    const unsigned sin_base = smem_u32(sin_f);
    const unsigned sw_base  = smem_u32(sw_u);

    const int tid = threadIdx.x;
    const int x0  = blockIdx.x * 32;
    const int y0  = blockIdx.y * 8;
    const int cog = blockIdx.z & 1;
    const int b   = blockIdx.z >> 1;
    const int wg  = tid >> 5;            // 0..7 -> local co base wg*4
    const int lane = tid & 31;
    const int rp  = lane >> 3;
    const int xs  = (lane & 7) * 4;
    const int co0 = cog*32 + wg*4;       // global first out-channel

    ull acc[2][2][4];                    // [co-pair][row][px]
#pragma unroll
    for (int j = 0; j < 2; ++j) {
        ull bv = pack2(bias[co0 + 2*j], bias[co0 + 2*j + 1]);
#pragma unroll
        for (int L = 0; L < 2; ++L)
#pragma unroll
            for (int px = 0; px < 4; ++px) acc[j][L][px] = bv;
    }

    const float* inb = in + (size_t)b*Cc*HW;

    unsigned hdst[11]; int hsrc[11]; unsigned hmask = 0;
#pragma unroll
    for (int q = 0; q < 11; ++q) {
        int e = tid + q*256;
        int cc  = e / 340;
        int idx = e - cc*340;
        int r   = idx / 34;
        int c2  = idx - r*34;
        int gy = y0 - 1 + r, gx = x0 - 1 + c2;
        bool ok = (e < 2720) &&
                  ((unsigned)gy < (unsigned)Hh) && ((unsigned)gx < (unsigned)Ww);
        hdst[q] = (unsigned)(cc*350 + r*35 + c2) * 4u;
        hsrc[q] = ok ? (cc*HW + gy*Ww + gx) : 0;
        if (ok) hmask |= 1u << q;
    }

    auto issue = [&](int bi, int cb) {
        const float* srcb = inb + (size_t)cb*HW;
        unsigned sbase = sin_base + bi*SIN_BYTES;
#pragma unroll
        for (int q = 0; q < 11; ++q) {
            if (q < 10 || tid < 160) {
                int ok4 = (hmask >> q) & 1;
                cp_async4(sbase + hdst[q], srcb + hsrc[q], ok4 << 2);
            }
        }
        // weights: 8ch x 9k x 16 pairs = 1152 ull = 576 x 16B, strided from [ci][k][32]
        unsigned wbase = sw_base + bi*SW_BYTES;
#pragma unroll
        for (int q = 0; q < 3; ++q) {
            int e = tid + q*256;
            if (q < 2 || tid < 64) {       // e < 576; e -> (ci, k, ph)
                int ci = e / 72;
                int r2 = e - ci*72;        // k*8 + ph
                const ull* src = wp + (size_t)(cb + ci)*288 + (r2 >> 3)*32 + cog*16 + (r2 & 7)*2;
                cp_async16(wbase + (unsigned)((ci*72 + r2)*16), src);
            }
        }
        cp_commit();
    };

    issue(0, 0);

    for (int s = 0; s < 8; ++s) {
        cp_wait<0>();
        __syncthreads();
        if (s < 7) issue((s + 1) & 1, (s + 1) * 8);

        const int bi = s & 1;
        const float* sif = sin_f + bi*SIN_F;
        const ull*   swu = sw_u  + bi*SW_U;
#pragma unroll
        for (int cc = 0; cc < 8; ++cc) {
#pragma unroll
            for (int r_in = 0; r_in < 4; ++r_in) {
                const int h = 2*rp + r_in;
                ull tp[6];
#pragma unroll
                for (int c = 0; c < 6; ++c) {
                    float t = sif[cc*350 + h*35 + xs + c];
                    tp[c] = dup2(t);
                }
#pragma unroll
                for (int L = 0; L < 2; ++L) {
                    if (r_in - L < 0 || r_in - L > 2) continue;
                    const int dy = r_in - L;
#pragma unroll
                    for (int dx = 0; dx < 3; ++dx) {
                        const int k = dy*3 + dx;
                        ulonglong2 w01 = *(const ulonglong2*)&swu[(cc*9 + k)*16 + wg*2];
#pragma unroll
                        for (int px = 0; px < 4; ++px) {
                            ull a = tp[px + dx];
                            acc[0][L][px] = ffma2(a, w01.x, acc[0][L][px]);
                            acc[1][L][px] = ffma2(a, w01.y, acc[1][L][px]);
                        }
                    }
                }
            }
        }
    }

    float a = 0.f;
    if (PRELU) a = a_ptr[0];
    const int x = x0 + xs;
#pragma unroll
    for (int j = 0; j < 2; ++j) {
#pragma unroll
        for (int L = 0; L < 2; ++L) {
            const int y = y0 + 2*rp + L;
            float v0[4], v1[4];
#pragma unroll
            for (int px = 0; px < 4; ++px) {
                unpack2(acc[j][L][px], v0[px], v1[px]);
                if (PRELU) {
                    v0[px] = (v0[px] >= 0.f) ? v0[px] : a*v0[px];
                    v1[px] = (v1[px] >= 0.f) ? v1[px] : a*v1[px];
                }
            }
            size_t o0 = ((size_t)(b*Cc + co0 + 2*j)*Hh + y)*Ww + x;
            size_t o1 = o0 + (size_t)HW;
            float4 a0 = make_float4(v0[0], v0[1], v0[2], v0[3]);
            float4 b0 = make_float4(v1[0], v1[1], v1[2], v1[3]);
            if (RESID) {
                float4 r0 = *(const float4*)(resid + o0);
                float4 r1 = *(const float4*)(resid + o1);
                a0.x += r0.x; a0.y += r0.y; a0.z += r0.z; a0.w += r0.w;
                b0.x += r1.x; b0.y += r1.y; b0.z += r1.z; b0.w += r1.w;
            }
            *(float4*)(out + o0) = a0;
            *(float4*)(out + o1) = b0;
        }
    }
}

// ---- fused kg5 + dynamic JBF (unchanged from R12) ----
#define KGJ_SMEM (288*64*4 + 288*4)

__global__ void __launch_bounds__(256, 2)
kgjbf_k(const float* __restrict__ y4, const float* __restrict__ w5,
        const float* __restrict__ b5, const float* __restrict__ img,
        float* __restrict__ out)
{
    extern __shared__ float smem[];
    float* s_w5 = smem;
    float* s_b5 = smem + 288*64;
    const int tid = threadIdx.x;
    const int ci0 = blockIdx.y*32;
    const int b = blockIdx.z;
    const int p = blockIdx.x * 256 + tid;
    const int y = p >> 8;
    const int x = p & 255;
    {
        float4* dst = (float4*)s_w5;
        for (int e = tid; e < 288*16; e += 256) {
            int row = e >> 4, q = e & 15;
            int f = ((row >> 5) << 6) + ci0 + (row & 31);
            dst[e] = ((const float4*)(w5 + (size_t)f*64))[q];
        }
        for (int e = tid; e < 288; e += 256)
            s_b5[e] = b5[((e >> 5) << 6) + ci0 + (e & 31)];
    }
    __syncthreads();
    ull yp[32];
    {
        const float* yb = y4 + (size_t)b*Cc*HW + p;
#pragma unroll
        for (int c2 = 0; c2 < 32; ++c2)
            yp[c2] = pack2(yb[(size_t)(2*c2)*HW], yb[(size_t)(2*c2+1)*HW]);
    }
    const float* ib = img + (size_t)b*Cc*HW;
    float* ob = out + ((size_t)b*Cc + ci0)*HW + p;

    int off[9]; unsigned okm = 0;
#pragma unroll
    for (int t = 0; t < 9; ++t) {
        int dy = t/3 - 1, dx = t - (t/3)*3 - 1;
        int yy = y + dy, xx = x + dx;
        off[t] = yy*Ww + xx;
        if ((unsigned)yy < (unsigned)Hh && (unsigned)xx < (unsigned)Ww) okm |= 1u << t;
    }
    const int tap00 = ci0 % 9;

    for (int j = 0; j < 32; ++j) {
        const int ci = ci0 + j;
        int tap0 = (tap00 + j) % 9;
        float acc = 0.f;
#pragma unroll
        for (int t = 0; t < 9; ++t) {
            int kk = t - tap0; kk += (kk < 0) ? 9 : 0;
            const int row = kk*32 + j;
            const ulonglong2* wrow = (const ulonglong2*)(s_w5 + row*64);
            ull p0 = 0ULL, p1 = 0ULL, p2 = 0ULL, p3 = 0ULL;
#pragma unroll
            for (int c4 = 0; c4 < 16; c4 += 4) {
                ulonglong2 wv0 = wrow[c4  ];
                ulonglong2 wv1 = wrow[c4+1];
                ulonglong2 wv2 = wrow[c4+2];
                ulonglong2 wv3 = wrow[c4+3];
                p0 = ffma2(yp[2*c4  ], wv0.x, p0);
                p1 = ffma2(yp[2*c4+1], wv0.y, p1);
                p2 = ffma2(yp[2*c4+2], wv1.x, p2);
                p3 = ffma2(yp[2*c4+3], wv1.y, p3);
                p0 = ffma2(yp[2*c4+4], wv2.x, p0);
                p1 = ffma2(yp[2*c4+5], wv2.y, p1);
                p2 = ffma2(yp[2*c4+6], wv3.x, p2);
                p3 = ffma2(yp[2*c4+7], wv3.y, p3);
            }
            p0 = add2(p0, p1); p2 = add2(p2, p3); p0 = add2(p0, p2);
            float lo, hi; unpack2(p0, lo, hi);
            float bik = lo + hi + s_b5[row];
            unsigned ch = (unsigned)(64*kk + ci - t) * 0x38E38E39u;
            float iv = 0.f;
            if ((okm >> t) & 1) iv = ib[(size_t)ch*HW + off[t]];
            acc = fmaf(bik, iv, acc);
        }
        ob[(size_t)j*HW] = acc;
    }
}

// ---------------------------------------------------------------------------
extern "C" void kernel_launch(void* const* d_in, const int* in_sizes, int n_in,
                              void* d_out, int out_size)
{
    const float* image   = (const float*)d_in[0];
    const float* guidance= (const float*)d_in[1];
    const float* tensor_w= (const float*)d_in[2];
    const float* tensor_b= (const float*)d_in[3];
    const float* a_jbf   = (const float*)d_in[4];
    const float* kg_w1   = (const float*)d_in[5];
    const float* kg_b1   = (const float*)d_in[6];
    const float* kg_w2   = (const float*)d_in[7];
    const float* kg_b2   = (const float*)d_in[8];
    const float* kg_w3   = (const float*)d_in[9];
    const float* kg_b3   = (const float*)d_in[10];
    const float* kg_w4   = (const float*)d_in[11];
    const float* kg_b4   = (const float*)d_in[12];
    const float* kg_w5   = (const float*)d_in[13];
    const float* kg_b5   = (const float*)d_in[14];
    const float* a_kg    = (const float*)d_in[15];
    const float* jbf_w1  = (const float*)d_in[16];
    const float* jbf_b1  = (const float*)d_in[17];
    const float* jbf_w2  = (const float*)d_in[18];
    const float* jbf_b2  = (const float*)d_in[19];
    float* out = (float*)d_out;

    float *A, *Bb;
    ull* WP;
    cudaGetSymbolAddress((void**)&A,  g_A);
    cudaGetSymbolAddress((void**)&Bb, g_B);
    cudaGetSymbolAddress((void**)&WP, g_WP);

    static bool attr_set = false;
    if (!attr_set) {
        cudaFuncSetAttribute(kgjbf_k, cudaFuncAttributeMaxDynamicSharedMemorySize, KGJ_SMEM);
        cudaFuncSetAttribute(conv3x3_k<true,false>,
                             cudaFuncAttributeMaxDynamicSharedMemorySize, CONV_SMEM);
        cudaFuncSetAttribute(conv3x3_k<false,true>,
                             cudaFuncAttributeMaxDynamicSharedMemorySize, CONV_SMEM);
        attr_set = true;
    }

    dim3 blk(256);
    dim3 gf(HW/512, 2, Bn);
    dim3 g3(Ww/32, Hh/8, 2*Bn);
    dim3 gj(HW/256, 2, Bn);

    pack_w_k<<<(110592 + 255)/256, blk>>>(kg_w1, kg_w2, kg_w3, kg_w4, jbf_w1, jbf_w2, WP);

    fuse1x1_k<<<gf, blk>>>(image, guidance, tensor_w, tensor_b, a_jbf, A);
    conv3x3_k<true,false><<<g3, blk, CONV_SMEM>>>(A,  WP + 0*18432, kg_b1, a_kg, nullptr, Bb);
    conv3x3_k<true,false><<<g3, blk, CONV_SMEM>>>(Bb, WP + 1*18432, kg_b2, a_kg, nullptr, A);
    conv3x3_k<true,false><<<g3, blk, CONV_SMEM>>>(A,  WP + 2*18432, kg_b3, a_kg, nullptr, Bb);
    conv3x3_k<true,false><<<g3, blk, CONV_SMEM>>>(Bb, WP + 3*18432, kg_b4, a_kg, nullptr, A);
    kgjbf_k<<<gj, blk, KGJ_SMEM>>>(A, kg_w5, kg_b5, image, Bb);
    conv3x3_k<true,false><<<g3, blk, CONV_SMEM>>>(Bb, WP + 4*18432, jbf_b1, a_jbf, nullptr, A);
    conv3x3_k<false,true><<<g3, blk, CONV_SMEM>>>(A,  WP + 5*18432, jbf_b2, nullptr, image, out);
}